// round 10
// baseline (speedup 1.0000x reference)
#include <cuda_runtime.h>
#include <cstdint>

#define Bb 256
#define Tt 1024
#define Vv 128
#define Hh 128

// Scratch (no allocations allowed).
__device__ unsigned char g_symbols[Bb * Tt];
__device__ float g_WihT[127 * Hh];
__device__ int g_len[Bb];
__device__ int g_assign[Bb];   // rank-ordered: g_assign[r] = batch element with length-rank r

// ---------------------------------------------------------------------------
// Kernel 0: lengths (blocks 0..255) + W_ih transpose (blocks 256..382).
// x[b,t,0] == 1.0 iff symbol==0 (pad). length = first pad.
// ---------------------------------------------------------------------------
__global__ void prep_kernel(const float* __restrict__ x,
                            const float* __restrict__ W_ih) {
    if (blockIdx.x >= Bb) {
        int f = blockIdx.x - Bb;   // 0..126
        int h = threadIdx.x;       // 0..127
        g_WihT[f * Hh + h] = W_ih[h * 127 + f];
        return;
    }
    __shared__ int smin;
    const int b = blockIdx.x;
    if (threadIdx.x == 0) smin = Tt;
    __syncthreads();
    int local = Tt;
    for (int t = threadIdx.x; t < Tt; t += 128) {
        float v = __ldcs(x + ((size_t)b * Tt + t) * Vv);
        if (v > 0.5f && t < local) local = t;
    }
#pragma unroll
    for (int o = 16; o; o >>= 1) {
        int other = __shfl_xor_sync(0xffffffffu, local, o);
        local = min(local, other);
    }
    if ((threadIdx.x & 31) == 0) atomicMin(&smin, local);
    __syncthreads();
    if (threadIdx.x == 0) g_len[b] = smin;
}

// ---------------------------------------------------------------------------
// Kernel 0b: sort by length (counting-rank). CTA i gets ranks {2i, 2i+1},
// so the two sequences co-resident in a CTA have near-identical lengths.
// ---------------------------------------------------------------------------
__global__ void schedule_kernel() {
    __shared__ int slen[Bb];
    int b = threadIdx.x;           // 256 threads
    slen[b] = g_len[b];
    __syncthreads();
    int Lb = slen[b];
    int rank = 0;
#pragma unroll 8
    for (int j = 0; j < Bb; j++) {
        int Lj = slen[j];
        rank += (Lj > Lb) || (Lj == Lb && j < b);
    }
    g_assign[rank] = b;
}

// ---------------------------------------------------------------------------
// Kernel 1: extract symbol index from one-hot rows. Warp per (b,t) row.
// ---------------------------------------------------------------------------
__global__ void sym_kernel(const float* __restrict__ x) {
    int row  = blockIdx.x * 8 + (threadIdx.x >> 5);
    int lane = threadIdx.x & 31;
    int b = row >> 10;        // row / Tt
    int t = row & (Tt - 1);
    if (t >= g_len[b]) {
        if (lane == 0) g_symbols[row] = 0;
        return;
    }
    float4 v = __ldcs(reinterpret_cast<const float4*>(x + (size_t)row * Vv) + lane);
    int idx = 0;
    if (v.x > 0.5f) idx = lane * 4 + 0;
    if (v.y > 0.5f) idx = lane * 4 + 1;
    if (v.z > 0.5f) idx = lane * 4 + 2;
    if (v.w > 0.5f) idx = lane * 4 + 3;
#pragma unroll
    for (int o = 16; o; o >>= 1) idx += __shfl_xor_sync(0xffffffffu, idx, o);
    if (lane == 0) g_symbols[row] = (unsigned char)idx;
}

// Packed dual-lane fp32 ops (Blackwell f32x2).
#define FMA2(d, a, b, c) \
    asm("fma.rn.f32x2 %0, %1, %2, %3;" : "=l"(d) : "l"(a), "l"(b), "l"(c))
#define ADD2(d, a, b) \
    asm("add.rn.f32x2 %0, %1, %2;" : "=l"(d) : "l"(a), "l"(b))
#define PACK2(d, lo, hi) \
    asm("mov.b64 %0, {%1, %2};" : "=l"(d) : "f"(lo), "f"(hi))

// Dot(W_row[tid], h) + init, h read broadcast from shared.
__device__ __forceinline__ float matvec(const float* __restrict__ hbuf,
                                        const unsigned long long* __restrict__ w2,
                                        float init) {
    const ulonglong2* h2 = reinterpret_cast<const ulonglong2*>(hbuf);
    unsigned long long a0, a1, a2, a3;
    PACK2(a0, init, 0.0f);
    a1 = 0; a2 = 0; a3 = 0;
#pragma unroll
    for (int c = 0; c < 16; c++) {
        ulonglong2 u = h2[2 * c];       // broadcast LDS.128
        ulonglong2 v = h2[2 * c + 1];   // broadcast LDS.128
        FMA2(a0, w2[4 * c + 0], u.x, a0);
        FMA2(a1, w2[4 * c + 1], u.y, a1);
        FMA2(a2, w2[4 * c + 2], v.x, a2);
        FMA2(a3, w2[4 * c + 3], v.y, a3);
    }
    ADD2(a0, a0, a1);
    ADD2(a2, a2, a3);
    ADD2(a0, a0, a2);
    return __uint_as_float((unsigned)a0) + __uint_as_float((unsigned)(a0 >> 32));
}

// ---------------------------------------------------------------------------
// Kernel 3: the RNN, TWO sequences per CTA. Thread i owns h[i] of both and
// keeps W_hh row i once in 64 packed-u64 registers. Barrier/tanh/loop cost
// is amortized across the pair; A's tanh overlaps B's FMA issue.
// 128 CTAs < 152 SMs -> every CTA solo on its SM.
// ---------------------------------------------------------------------------
__global__ __launch_bounds__(128, 1) void rnn_kernel(
    const float* __restrict__ W_hh,
    const float* __restrict__ b_ih,
    const float* __restrict__ b_hh,
    const float* __restrict__ W_out,
    const float* __restrict__ b_out,
    float* __restrict__ out)
{
    __shared__ __align__(16) float hbufA[2][Hh];
    __shared__ __align__(16) float hbufB[2][Hh];
    __shared__ __align__(16) unsigned char ssymA[Tt];
    __shared__ __align__(16) unsigned char ssymB[Tt];
    __shared__ float redA[2][Hh];
    __shared__ float redB[2][Hh];

    const int bA  = g_assign[2 * blockIdx.x + 0];
    const int bB  = g_assign[2 * blockIdx.x + 1];
    const int tid = threadIdx.x;

    // Stage both symbol rows into shared (2 KB).
    {
        const uint4* srcA = reinterpret_cast<const uint4*>(g_symbols + (size_t)bA * Tt);
        const uint4* srcB = reinterpret_cast<const uint4*>(g_symbols + (size_t)bB * Tt);
        uint4* dstA = reinterpret_cast<uint4*>(ssymA);
        uint4* dstB = reinterpret_cast<uint4*>(ssymB);
        for (int i = tid; i < Tt / 16; i += 128) { dstA[i] = srcA[i]; dstB[i] = srcB[i]; }
    }

    // W_hh row tid -> 64 packed f32x2 registers (shared by both sequences).
    unsigned long long w2[64];
    {
        const ulonglong2* wr = reinterpret_cast<const ulonglong2*>(W_hh + (size_t)tid * Hh);
#pragma unroll
        for (int c = 0; c < 32; c++) {
            ulonglong2 u = wr[c];
            w2[2 * c]     = u.x;
            w2[2 * c + 1] = u.y;
        }
    }

    const float bsum = b_ih[tid] + b_hh[tid];
    hbufA[0][tid] = 0.0f;
    hbufB[0][tid] = 0.0f;
    __syncthreads();

    int   p  = 0;
    int   t  = 0;
    int   sA = ssymA[0], sB = ssymB[0];
    float preA = (sA > 0) ? g_WihT[(sA - 1) * Hh + tid] : 0.0f;
    float preB = (sB > 0) ? g_WihT[(sB - 1) * Hh + tid] : 0.0f;
    float hmyA = 0.0f, hmyB = 0.0f;

    while (sA > 0 || sB > 0) {
        // Compute both matvecs unconditionally (no divergence hardware-wise:
        // conditions are CTA-uniform; this removes branch machinery and lets
        // B's FMA issue overlap A's latency tail). Commit is guarded.
        float zA = matvec(hbufA[p], w2, preA + bsum);
        float zB = matvec(hbufB[p], w2, preB + bsum);
        if (sA > 0) {
            float e = __expf(2.0f * zA);
            hmyA = 1.0f - __fdividef(2.0f, e + 1.0f);   // tanh
        }
        if (sB > 0) {
            float e = __expf(2.0f * zB);
            hmyB = 1.0f - __fdividef(2.0f, e + 1.0f);
        }

        // Prefetch next step before the barrier.
        t++;
        int snA = (t < Tt) ? (int)ssymA[t] : 0;
        int snB = (t < Tt) ? (int)ssymB[t] : 0;
        float prenA = (snA > 0) ? g_WihT[(snA - 1) * Hh + tid] : 0.0f;
        float prenB = (snB > 0) ? g_WihT[(snB - 1) * Hh + tid] : 0.0f;

        hbufA[p ^ 1][tid] = hmyA;
        hbufB[p ^ 1][tid] = hmyB;
        __syncthreads();
        p ^= 1;
        sA = snA; sB = snB;
        preA = prenA; preB = prenB;
    }

    // Epilogue for both sequences.
    out[2 * Bb + bA * Hh + tid] = hmyA;            // hidden (1,B,H) at offset 512
    out[2 * Bb + bB * Hh + tid] = hmyB;
    float w0 = W_out[tid], w1 = W_out[Hh + tid];
    redA[0][tid] = w0 * hmyA;  redA[1][tid] = w1 * hmyA;
    redB[0][tid] = w0 * hmyB;  redB[1][tid] = w1 * hmyB;
    __syncthreads();
    if (tid == 0) {
        float l0 = b_out[0], l1 = b_out[1];
#pragma unroll 8
        for (int i = 0; i < Hh; i++) { l0 += redA[0][i]; l1 += redA[1][i]; }
        float m  = fmaxf(l0, l1);
        float e0 = __expf(l0 - m), e1 = __expf(l1 - m);
        float inv = __fdividef(1.0f, e0 + e1);
        out[bA * 2 + 0] = e0 * inv;                // fed (B,2) at offset 0
        out[bA * 2 + 1] = e1 * inv;
    }
    if (tid == 32) {
        float l0 = b_out[0], l1 = b_out[1];
#pragma unroll 8
        for (int i = 0; i < Hh; i++) { l0 += redB[0][i]; l1 += redB[1][i]; }
        float m  = fmaxf(l0, l1);
        float e0 = __expf(l0 - m), e1 = __expf(l1 - m);
        float inv = __fdividef(1.0f, e0 + e1);
        out[bB * 2 + 0] = e0 * inv;
        out[bB * 2 + 1] = e1 * inv;
    }
}

// ---------------------------------------------------------------------------
extern "C" void kernel_launch(void* const* d_in, const int* in_sizes, int n_in,
                              void* d_out, int out_size) {
    (void)in_sizes; (void)n_in; (void)out_size;
    const float* x     = (const float*)d_in[0];
    const float* W_ih  = (const float*)d_in[1];
    const float* W_hh  = (const float*)d_in[2];
    const float* b_ih  = (const float*)d_in[3];
    const float* b_hh  = (const float*)d_in[4];
    const float* W_out = (const float*)d_in[5];
    const float* b_out = (const float*)d_in[6];
    float* out = (float*)d_out;

    prep_kernel<<<Bb + 127, 128>>>(x, W_ih);
    schedule_kernel<<<1, Bb>>>();
    sym_kernel<<<(Bb * Tt) / 8, 256>>>(x);
    rnn_kernel<<<Bb / 2, 128>>>(W_hh, b_ih, b_hh, W_out, b_out, out);
}

// round 11
// speedup vs baseline: 1.5805x; 1.5805x over previous
#include <cuda_runtime.h>
#include <cstdint>

#define Bb 256
#define Tt 1024
#define Vv 128
#define Hh 128
#define NSM 152          // GB300 sm_103a active SMs
#define NSOLO (Bb - NSM) // 104 paired bids -> 48 solo bids (104..151)

// Scratch (no allocations allowed).
__device__ unsigned char g_symbols[Bb * Tt];
__device__ float g_WihT[127 * Hh];
__device__ int g_len[Bb];
__device__ int g_assign[Bb];   // bid -> batch element

// ---------------------------------------------------------------------------
// Kernel 0: lengths (blocks 0..255) + W_ih transpose (blocks 256..382).
// x[b,t,0] == 1.0 iff symbol==0 (pad). length = first pad.
// ---------------------------------------------------------------------------
__global__ void prep_kernel(const float* __restrict__ x,
                            const float* __restrict__ W_ih) {
    if (blockIdx.x >= Bb) {
        int f = blockIdx.x - Bb;   // 0..126
        int h = threadIdx.x;       // 0..127
        g_WihT[f * Hh + h] = W_ih[h * 127 + f];
        return;
    }
    __shared__ int smin;
    const int b = blockIdx.x;
    if (threadIdx.x == 0) smin = Tt;
    __syncthreads();
    int local = Tt;
    for (int t = threadIdx.x; t < Tt; t += 128) {
        float v = __ldcs(x + ((size_t)b * Tt + t) * Vv);
        if (v > 0.5f && t < local) local = t;
    }
#pragma unroll
    for (int o = 16; o; o >>= 1) {
        int other = __shfl_xor_sync(0xffffffffu, local, o);
        local = min(local, other);
    }
    if ((threadIdx.x & 31) == 0) atomicMin(&smin, local);
    __syncthreads();
    if (threadIdx.x == 0) g_len[b] = smin;
}

// ---------------------------------------------------------------------------
// Kernel 0b: length-aware CTA->SM schedule (proven in R7).
// Classic placement: bids b and b+NSM co-resident; bids 104..151 solo.
// Solo slots get the longest sequences; the rest pair anti-sorted.
// ---------------------------------------------------------------------------
__global__ void schedule_kernel() {
    __shared__ int slen[Bb];
    int b = threadIdx.x;           // 256 threads
    slen[b] = g_len[b];
    __syncthreads();
    int Lb = slen[b];
    int rank = 0;
#pragma unroll 8
    for (int j = 0; j < Bb; j++) {
        int Lj = slen[j];
        rank += (Lj > Lb) || (Lj == Lb && j < b);
    }
    int slot;
    if (rank < NSOLO)            slot = (NSM - NSOLO) + rank;   // 104..151 solo
    else if (rank < NSM)         slot = rank - NSOLO;           // 0..103
    else                         slot = (Bb - 1 - rank) + NSM;  // 152..255
    g_assign[slot] = b;
}

// ---------------------------------------------------------------------------
// Kernel 1: extract symbol index from one-hot rows. Warp per (b,t) row.
// ---------------------------------------------------------------------------
__global__ void sym_kernel(const float* __restrict__ x) {
    int row  = blockIdx.x * 8 + (threadIdx.x >> 5);
    int lane = threadIdx.x & 31;
    int b = row >> 10;        // row / Tt
    int t = row & (Tt - 1);
    if (t >= g_len[b]) {
        if (lane == 0) g_symbols[row] = 0;
        return;
    }
    float4 v = __ldcs(reinterpret_cast<const float4*>(x + (size_t)row * Vv) + lane);
    int idx = 0;
    if (v.x > 0.5f) idx = lane * 4 + 0;
    if (v.y > 0.5f) idx = lane * 4 + 1;
    if (v.z > 0.5f) idx = lane * 4 + 2;
    if (v.w > 0.5f) idx = lane * 4 + 3;
#pragma unroll
    for (int o = 16; o; o >>= 1) idx += __shfl_xor_sync(0xffffffffu, idx, o);
    if (lane == 0) g_symbols[row] = (unsigned char)idx;
}

// Packed dual-lane fp32 ops (Blackwell f32x2) + HW tanh.
#define FMA2(d, a, b, c) \
    asm("fma.rn.f32x2 %0, %1, %2, %3;" : "=l"(d) : "l"(a), "l"(b), "l"(c))
#define ADD2(d, a, b) \
    asm("add.rn.f32x2 %0, %1, %2;" : "=l"(d) : "l"(a), "l"(b))
#define PACK2(d, lo, hi) \
    asm("mov.b64 %0, {%1, %2};" : "=l"(d) : "f"(lo), "f"(hi))
#define TANHF(d, x) \
    asm("tanh.approx.f32 %0, %1;" : "=f"(d) : "f"(x))

// ---------------------------------------------------------------------------
// Kernel 3: the RNN. One CTA per (scheduled) batch element, 128 threads;
// thread i owns h[i], W_hh row i in 64 packed-u64 registers.
// Critical path per step: BAR -> LDS -> FMA issue (256-cyc pipe floor)
// -> tail adds -> MUFU.TANH -> STS -> (prefetch in drain window) -> BAR.
// ---------------------------------------------------------------------------
__global__ __launch_bounds__(128, 2) void rnn_kernel(
    const float* __restrict__ W_hh,
    const float* __restrict__ b_ih,
    const float* __restrict__ b_hh,
    const float* __restrict__ W_out,
    const float* __restrict__ b_out,
    float* __restrict__ out)
{
    __shared__ __align__(16) float hb[2][Hh];
    __shared__ __align__(16) unsigned char ssym[Tt];
    __shared__ float red[2][Hh];

    const int b   = g_assign[blockIdx.x];
    const int tid = threadIdx.x;

    // Stage this row's symbols into shared (1 KB).
    {
        const uint4* src = reinterpret_cast<const uint4*>(g_symbols + (size_t)b * Tt);
        uint4* dst = reinterpret_cast<uint4*>(ssym);
        for (int i = tid; i < Tt / 16; i += 128) dst[i] = src[i];
    }

    // W_hh row tid -> 64 packed f32x2 registers.
    unsigned long long w2[64];
    {
        const ulonglong2* wr = reinterpret_cast<const ulonglong2*>(W_hh + (size_t)tid * Hh);
#pragma unroll
        for (int c = 0; c < 32; c++) {
            ulonglong2 u = wr[c];
            w2[2 * c]     = u.x;
            w2[2 * c + 1] = u.y;
        }
    }

    const float bsum = b_ih[tid] + b_hh[tid];
    hb[0][tid] = 0.0f;
    __syncthreads();

    int   p = 0;
    int   t = 0;
    int   s = ssym[0];
    // pre includes bsum (computed off the critical path).
    float pre = (s > 0) ? (g_WihT[(s - 1) * Hh + tid] + bsum) : 0.0f;

    while (s > 0) {
        const ulonglong2* h2 = reinterpret_cast<const ulonglong2*>(hb[p]);
        unsigned long long a0, a1, a2, a3;
        PACK2(a0, pre, 0.0f);
        a1 = 0; a2 = 0; a3 = 0;
#pragma unroll
        for (int c = 0; c < 16; c++) {
            ulonglong2 u = h2[2 * c];       // broadcast LDS.128
            ulonglong2 v = h2[2 * c + 1];   // broadcast LDS.128
            FMA2(a0, w2[4 * c + 0], u.x, a0);
            FMA2(a1, w2[4 * c + 1], u.y, a1);
            FMA2(a2, w2[4 * c + 2], v.x, a2);
            FMA2(a3, w2[4 * c + 3], v.y, a3);
        }
        ADD2(a0, a0, a1);
        ADD2(a2, a2, a3);
        ADD2(a0, a0, a2);
        float z = __uint_as_float((unsigned)a0)
                + __uint_as_float((unsigned)(a0 >> 32));
        float hn;
        TANHF(hn, z);                 // MUFU.TANH, lat ~16

        // Commit h first, then prefetch inside the barrier-drain window.
        hb[p ^ 1][tid] = hn;

        t++;
        int sn = (t < Tt) ? (int)ssym[t] : 0;
        float pren = (sn > 0) ? (g_WihT[(sn - 1) * Hh + tid] + bsum) : 0.0f;

        __syncthreads();
        p ^= 1;
        s = sn;
        pre = pren;
    }

    // Epilogue: h_last is in hb[p].
    float hv = hb[p][tid];
    out[2 * Bb + b * Hh + tid] = hv;               // hidden (1,B,H) at offset 512
    red[0][tid] = W_out[tid] * hv;                 // W_out row 0
    red[1][tid] = W_out[Hh + tid] * hv;            // W_out row 1
    __syncthreads();
    if (tid == 0) {
        float l0 = b_out[0], l1 = b_out[1];
#pragma unroll 8
        for (int i = 0; i < Hh; i++) { l0 += red[0][i]; l1 += red[1][i]; }
        float m  = fmaxf(l0, l1);
        float e0 = __expf(l0 - m), e1 = __expf(l1 - m);
        float inv = __fdividef(1.0f, e0 + e1);
        out[b * 2 + 0] = e0 * inv;                 // fed (B,2) at offset 0
        out[b * 2 + 1] = e1 * inv;
    }
}

// ---------------------------------------------------------------------------
extern "C" void kernel_launch(void* const* d_in, const int* in_sizes, int n_in,
                              void* d_out, int out_size) {
    (void)in_sizes; (void)n_in; (void)out_size;
    const float* x     = (const float*)d_in[0];
    const float* W_ih  = (const float*)d_in[1];
    const float* W_hh  = (const float*)d_in[2];
    const float* b_ih  = (const float*)d_in[3];
    const float* b_hh  = (const float*)d_in[4];
    const float* W_out = (const float*)d_in[5];
    const float* b_out = (const float*)d_in[6];
    float* out = (float*)d_out;

    prep_kernel<<<Bb + 127, 128>>>(x, W_ih);
    schedule_kernel<<<1, Bb>>>();
    sym_kernel<<<(Bb * Tt) / 8, 256>>>(x);
    rnn_kernel<<<Bb, 128>>>(W_hh, b_ih, b_hh, W_out, b_out, out);
}

// round 12
// speedup vs baseline: 2.0402x; 1.2909x over previous
#include <cuda_runtime.h>
#include <cstdint>

#define Bb 256
#define Tt 1024
#define Vv 128
#define Hh 128
#define NSM 152          // GB300 sm_103a active SMs
#define NSOLO (Bb - NSM) // 104 paired bids -> 48 solo bids (104..151)

// Scratch (no allocations allowed).
__device__ unsigned char g_symbols[Bb * Tt];
__device__ float g_Wtbl[128 * Hh];   // row s = W_ih[:, s-1]; row 0 = zeros
__device__ int g_len[Bb];
__device__ int g_assign[Bb];   // bid -> batch element

// ---------------------------------------------------------------------------
// Kernel 0: lengths (blocks 0..255) + W_ih table build (blocks 256..383).
// x[b,t,0] == 1.0 iff symbol==0 (pad). length = first pad.
// ---------------------------------------------------------------------------
__global__ void prep_kernel(const float* __restrict__ x,
                            const float* __restrict__ W_ih) {
    if (blockIdx.x >= Bb) {
        int s = blockIdx.x - Bb;   // 0..127 (table row)
        int h = threadIdx.x;       // 0..127
        g_Wtbl[s * Hh + h] = (s == 0) ? 0.0f : W_ih[h * 127 + (s - 1)];
        return;
    }
    __shared__ int smin;
    const int b = blockIdx.x;
    if (threadIdx.x == 0) smin = Tt;
    __syncthreads();
    int local = Tt;
    for (int t = threadIdx.x; t < Tt; t += 128) {
        float v = __ldcs(x + ((size_t)b * Tt + t) * Vv);
        if (v > 0.5f && t < local) local = t;
    }
#pragma unroll
    for (int o = 16; o; o >>= 1) {
        int other = __shfl_xor_sync(0xffffffffu, local, o);
        local = min(local, other);
    }
    if ((threadIdx.x & 31) == 0) atomicMin(&smin, local);
    __syncthreads();
    if (threadIdx.x == 0) g_len[b] = smin;
}

// ---------------------------------------------------------------------------
// Kernel 0b: length-aware CTA->SM schedule (proven in R7).
// Classic placement: bids b and b+NSM co-resident; bids 104..151 solo.
// Solo slots get the longest sequences; the rest pair anti-sorted.
// ---------------------------------------------------------------------------
__global__ void schedule_kernel() {
    __shared__ int slen[Bb];
    int b = threadIdx.x;           // 256 threads
    slen[b] = g_len[b];
    __syncthreads();
    int Lb = slen[b];
    int rank = 0;
#pragma unroll 8
    for (int j = 0; j < Bb; j++) {
        int Lj = slen[j];
        rank += (Lj > Lb) || (Lj == Lb && j < b);
    }
    int slot;
    if (rank < NSOLO)            slot = (NSM - NSOLO) + rank;   // 104..151 solo
    else if (rank < NSM)         slot = rank - NSOLO;           // 0..103
    else                         slot = (Bb - 1 - rank) + NSM;  // 152..255
    g_assign[slot] = b;
}

// ---------------------------------------------------------------------------
// Kernel 1: extract symbol index from one-hot rows. Warp per (b,t) row.
// ---------------------------------------------------------------------------
__global__ void sym_kernel(const float* __restrict__ x) {
    int row  = blockIdx.x * 8 + (threadIdx.x >> 5);
    int lane = threadIdx.x & 31;
    int b = row >> 10;        // row / Tt
    int t = row & (Tt - 1);
    if (t >= g_len[b]) {
        if (lane == 0) g_symbols[row] = 0;
        return;
    }
    float4 v = __ldcs(reinterpret_cast<const float4*>(x + (size_t)row * Vv) + lane);
    int idx = 0;
    if (v.x > 0.5f) idx = lane * 4 + 0;
    if (v.y > 0.5f) idx = lane * 4 + 1;
    if (v.z > 0.5f) idx = lane * 4 + 2;
    if (v.w > 0.5f) idx = lane * 4 + 3;
#pragma unroll
    for (int o = 16; o; o >>= 1) idx += __shfl_xor_sync(0xffffffffu, idx, o);
    if (lane == 0) g_symbols[row] = (unsigned char)idx;
}

// Packed dual-lane fp32 ops (Blackwell f32x2) + HW tanh.
#define FMA2(d, a, b, c) \
    asm("fma.rn.f32x2 %0, %1, %2, %3;" : "=l"(d) : "l"(a), "l"(b), "l"(c))
#define ADD2(d, a, b) \
    asm("add.rn.f32x2 %0, %1, %2;" : "=l"(d) : "l"(a), "l"(b))
#define PACK2(d, lo, hi) \
    asm("mov.b64 %0, {%1, %2};" : "=l"(d) : "f"(lo), "f"(hi))
#define TANHF(d, x) \
    asm("tanh.approx.f32 %0, %1;" : "=f"(d) : "f"(x))

// ---------------------------------------------------------------------------
// Kernel 3: the RNN. One CTA per (scheduled) batch element, 128 threads;
// thread i owns h[i], W_hh row i in 64 packed-u64 registers.
// Runs 2 symbols ahead: the pre-activation gather for step t+1 is ISSUED at
// the top of step t (hidden under the FMA issue phase); symbol t+2 via LDS.
// Zero row 0 in g_Wtbl removes all predicates from the gather.
// ---------------------------------------------------------------------------
__global__ __launch_bounds__(128, 2) void rnn_kernel(
    const float* __restrict__ W_hh,
    const float* __restrict__ b_ih,
    const float* __restrict__ b_hh,
    const float* __restrict__ W_out,
    const float* __restrict__ b_out,
    float* __restrict__ out)
{
    __shared__ __align__(16) float hb[2][Hh];
    __shared__ __align__(16) unsigned char ssym[Tt + 16];
    __shared__ float red[2][Hh];

    const int b   = g_assign[blockIdx.x];
    const int tid = threadIdx.x;

    // Stage this row's symbols into shared (1 KB) + zero pad tail.
    {
        const uint4* src = reinterpret_cast<const uint4*>(g_symbols + (size_t)b * Tt);
        uint4* dst = reinterpret_cast<uint4*>(ssym);
        for (int i = tid; i < Tt / 16; i += 128) dst[i] = src[i];
        if (tid == 0) *reinterpret_cast<uint4*>(ssym + Tt) = make_uint4(0, 0, 0, 0);
    }

    // W_hh row tid -> 64 packed f32x2 registers.
    unsigned long long w2[64];
    {
        const ulonglong2* wr = reinterpret_cast<const ulonglong2*>(W_hh + (size_t)tid * Hh);
#pragma unroll
        for (int c = 0; c < 32; c++) {
            ulonglong2 u = wr[c];
            w2[2 * c]     = u.x;
            w2[2 * c + 1] = u.y;
        }
    }

    const float bsum = b_ih[tid] + b_hh[tid];
    hb[0][tid] = 0.0f;
    __syncthreads();

    int   p  = 0;
    int   t  = 0;
    int   s  = ssym[0];              // symbol for current step
    int   sn = ssym[1];              // symbol for next step
    float pre = g_Wtbl[(s << 7) + tid] + bsum;   // pre-activation, current step

    while (s > 0) {
        // ---- issue next-step gather EARLY (hides under FMA phase) ----
        float pren = g_Wtbl[(sn << 7) + tid];    // row 0 = zeros if sn==0
        int   sn2  = ssym[t + 2];

        const ulonglong2* h2 = reinterpret_cast<const ulonglong2*>(hb[p]);
        unsigned long long a0, a1, a2, a3;
        PACK2(a0, pre, 0.0f);
        a1 = 0; a2 = 0; a3 = 0;
#pragma unroll
        for (int c = 0; c < 16; c++) {
            ulonglong2 u = h2[2 * c];       // broadcast LDS.128
            ulonglong2 v = h2[2 * c + 1];   // broadcast LDS.128
            FMA2(a0, w2[4 * c + 0], u.x, a0);
            FMA2(a1, w2[4 * c + 1], u.y, a1);
            FMA2(a2, w2[4 * c + 2], v.x, a2);
            FMA2(a3, w2[4 * c + 3], v.y, a3);
        }
        ADD2(a0, a0, a1);
        ADD2(a2, a2, a3);
        ADD2(a0, a0, a2);
        float z = __uint_as_float((unsigned)a0)
                + __uint_as_float((unsigned)(a0 >> 32));
        float hn;
        TANHF(hn, z);                 // MUFU.TANH

        hb[p ^ 1][tid] = hn;
        __syncthreads();

        p ^= 1;
        t++;
        s  = sn;
        sn = sn2;
        pre = pren + bsum;
    }

    // Epilogue: h_last is in hb[p].
    float hv = hb[p][tid];
    out[2 * Bb + b * Hh + tid] = hv;               // hidden (1,B,H) at offset 512
    red[0][tid] = W_out[tid] * hv;                 // W_out row 0
    red[1][tid] = W_out[Hh + tid] * hv;            // W_out row 1
    __syncthreads();
    if (tid == 0) {
        float l0 = b_out[0], l1 = b_out[1];
#pragma unroll 8
        for (int i = 0; i < Hh; i++) { l0 += red[0][i]; l1 += red[1][i]; }
        float m  = fmaxf(l0, l1);
        float e0 = __expf(l0 - m), e1 = __expf(l1 - m);
        float inv = __fdividef(1.0f, e0 + e1);
        out[b * 2 + 0] = e0 * inv;                 // fed (B,2) at offset 0
        out[b * 2 + 1] = e1 * inv;
    }
}

// ---------------------------------------------------------------------------
extern "C" void kernel_launch(void* const* d_in, const int* in_sizes, int n_in,
                              void* d_out, int out_size) {
    (void)in_sizes; (void)n_in; (void)out_size;
    const float* x     = (const float*)d_in[0];
    const float* W_ih  = (const float*)d_in[1];
    const float* W_hh  = (const float*)d_in[2];
    const float* b_ih  = (const float*)d_in[3];
    const float* b_hh  = (const float*)d_in[4];
    const float* W_out = (const float*)d_in[5];
    const float* b_out = (const float*)d_in[6];
    float* out = (float*)d_out;

    prep_kernel<<<Bb + 128, 128>>>(x, W_ih);
    schedule_kernel<<<1, Bb>>>();
    sym_kernel<<<(Bb * Tt) / 8, 256>>>(x);
    rnn_kernel<<<Bb, 128>>>(W_hh, b_ih, b_hh, W_out, b_out, out);
}

// round 16
// speedup vs baseline: 2.0503x; 1.0049x over previous
#include <cuda_runtime.h>
#include <cstdint>

#define Bb 256
#define Tt 1024
#define Vv 128
#define Hh 128
#define NSM 152          // GB300 sm_103a active SMs
#define NSOLO (Bb - NSM) // 104 paired bids -> 48 solo bids (104..151)

// Scratch (no allocations allowed).
__device__ unsigned char g_symbols[Bb * Tt];
__device__ float g_Wtbl[128 * Hh];   // row s = W_ih[:, s-1]; row 0 = zeros
__device__ int g_len[Bb];
__device__ int g_assign[Bb];   // bid -> batch element

// ---------------------------------------------------------------------------
// Kernel 0: lengths (blocks 0..255) + W_ih table build (blocks 256..383).
// x[b,t,0] == 1.0 iff symbol==0 (pad). length = first pad.
// ---------------------------------------------------------------------------
__global__ void prep_kernel(const float* __restrict__ x,
                            const float* __restrict__ W_ih) {
    if (blockIdx.x >= Bb) {
        int s = blockIdx.x - Bb;   // 0..127 (table row)
        int h = threadIdx.x;       // 0..127
        g_Wtbl[s * Hh + h] = (s == 0) ? 0.0f : W_ih[h * 127 + (s - 1)];
        return;
    }
    __shared__ int smin;
    const int b = blockIdx.x;
    if (threadIdx.x == 0) smin = Tt;
    __syncthreads();
    int local = Tt;
    for (int t = threadIdx.x; t < Tt; t += 128) {
        float v = __ldcs(x + ((size_t)b * Tt + t) * Vv);
        if (v > 0.5f && t < local) local = t;
    }
#pragma unroll
    for (int o = 16; o; o >>= 1) {
        int other = __shfl_xor_sync(0xffffffffu, local, o);
        local = min(local, other);
    }
    if ((threadIdx.x & 31) == 0) atomicMin(&smin, local);
    __syncthreads();
    if (threadIdx.x == 0) g_len[b] = smin;
}

// ---------------------------------------------------------------------------
// Kernel 0b: length-aware CTA->SM schedule (proven in R7).
// Classic placement: bids b and b+NSM co-resident; bids 104..151 solo.
// Solo slots get the longest sequences; the rest pair anti-sorted.
// ---------------------------------------------------------------------------
__global__ void schedule_kernel() {
    __shared__ int slen[Bb];
    int b = threadIdx.x;           // 256 threads
    slen[b] = g_len[b];
    __syncthreads();
    int Lb = slen[b];
    int rank = 0;
#pragma unroll 8
    for (int j = 0; j < Bb; j++) {
        int Lj = slen[j];
        rank += (Lj > Lb) || (Lj == Lb && j < b);
    }
    int slot;
    if (rank < NSOLO)            slot = (NSM - NSOLO) + rank;   // 104..151 solo
    else if (rank < NSM)         slot = rank - NSOLO;           // 0..103
    else                         slot = (Bb - 1 - rank) + NSM;  // 152..255
    g_assign[slot] = b;
}

// ---------------------------------------------------------------------------
// Kernel 1: extract symbol index from one-hot rows. Warp per (b,t) row.
// ---------------------------------------------------------------------------
__global__ void sym_kernel(const float* __restrict__ x) {
    int row  = blockIdx.x * 8 + (threadIdx.x >> 5);
    int lane = threadIdx.x & 31;
    int b = row >> 10;        // row / Tt
    int t = row & (Tt - 1);
    if (t >= g_len[b]) {
        if (lane == 0) g_symbols[row] = 0;
        return;
    }
    float4 v = __ldcs(reinterpret_cast<const float4*>(x + (size_t)row * Vv) + lane);
    int idx = 0;
    if (v.x > 0.5f) idx = lane * 4 + 0;
    if (v.y > 0.5f) idx = lane * 4 + 1;
    if (v.z > 0.5f) idx = lane * 4 + 2;
    if (v.w > 0.5f) idx = lane * 4 + 3;
#pragma unroll
    for (int o = 16; o; o >>= 1) idx += __shfl_xor_sync(0xffffffffu, idx, o);
    if (lane == 0) g_symbols[row] = (unsigned char)idx;
}

// Packed dual-lane fp32 ops (Blackwell f32x2) + HW tanh.
#define FMA2(d, a, b, c) \
    asm("fma.rn.f32x2 %0, %1, %2, %3;" : "=l"(d) : "l"(a), "l"(b), "l"(c))
#define ADD2(d, a, b) \
    asm("add.rn.f32x2 %0, %1, %2;" : "=l"(d) : "l"(a), "l"(b))
#define PACK2(d, lo, hi) \
    asm("mov.b64 %0, {%1, %2};" : "=l"(d) : "f"(lo), "f"(hi))
#define TANHF(d, x) \
    asm("tanh.approx.f32 %0, %1;" : "=f"(d) : "f"(x))

// ---------------------------------------------------------------------------
// Kernel 3: the RNN. One CTA per (scheduled) batch element, 128 threads;
// thread i owns h[i], W_hh row i in 64 packed-u64 registers.
// Matvec in two half-batches: 16 x LDS.128 into hreg (MLP=16), 32 FMA2,
// reload, 32 FMA2. Peak regs ~222, no spill; LDS latency paid ~2x/step.
// Runs 2 symbols ahead: the gather for step t+1 issues at the top of step t.
// ---------------------------------------------------------------------------
__global__ __launch_bounds__(128, 2) void rnn_kernel(
    const float* __restrict__ W_hh,
    const float* __restrict__ b_ih,
    const float* __restrict__ b_hh,
    const float* __restrict__ W_out,
    const float* __restrict__ b_out,
    float* __restrict__ out)
{
    __shared__ __align__(16) float hb[2][Hh];
    __shared__ __align__(16) unsigned char ssym[Tt + 16];
    __shared__ float red[2][Hh];

    const int b   = g_assign[blockIdx.x];
    const int tid = threadIdx.x;

    // Stage this row's symbols into shared (1 KB) + zero pad tail.
    {
        const uint4* src = reinterpret_cast<const uint4*>(g_symbols + (size_t)b * Tt);
        uint4* dst = reinterpret_cast<uint4*>(ssym);
        for (int i = tid; i < Tt / 16; i += 128) dst[i] = src[i];
        if (tid == 0) *reinterpret_cast<uint4*>(ssym + Tt) = make_uint4(0, 0, 0, 0);
    }

    // W_hh row tid -> 64 packed f32x2 registers.
    unsigned long long w2[64];
    {
        const ulonglong2* wr = reinterpret_cast<const ulonglong2*>(W_hh + (size_t)tid * Hh);
#pragma unroll
        for (int c = 0; c < 32; c++) {
            ulonglong2 u = wr[c];
            w2[2 * c]     = u.x;
            w2[2 * c + 1] = u.y;
        }
    }

    const float bsum = b_ih[tid] + b_hh[tid];
    hb[0][tid] = 0.0f;
    __syncthreads();

    int   p  = 0;
    int   t  = 0;
    int   s  = ssym[0];              // symbol for current step
    int   sn = ssym[1];              // symbol for next step
    float pre = g_Wtbl[(s << 7) + tid] + bsum;   // pre-activation, current step

    while (s > 0) {
        // ---- issue next-step gather EARLY (hides under FMA phase) ----
        float pren = g_Wtbl[(sn << 7) + tid];    // row 0 = zeros if sn==0
        int   sn2  = ssym[t + 2];

        const ulonglong2* h2 = reinterpret_cast<const ulonglong2*>(hb[p]);
        unsigned long long hreg[32];
        unsigned long long a0, a1, a2, a3;
        PACK2(a0, pre, 0.0f);
        a1 = 0; a2 = 0; a3 = 0;

        // ---- half-batch 0: 16 x LDS.128, then 32 reg-only FMA2 ----
#pragma unroll
        for (int c = 0; c < 8; c++) {
            ulonglong2 u = h2[2 * c];
            ulonglong2 v = h2[2 * c + 1];
            hreg[4 * c + 0] = u.x;
            hreg[4 * c + 1] = u.y;
            hreg[4 * c + 2] = v.x;
            hreg[4 * c + 3] = v.y;
        }
#pragma unroll
        for (int c = 0; c < 8; c++) {
            FMA2(a0, w2[4 * c + 0], hreg[4 * c + 0], a0);
            FMA2(a1, w2[4 * c + 1], hreg[4 * c + 1], a1);
            FMA2(a2, w2[4 * c + 2], hreg[4 * c + 2], a2);
            FMA2(a3, w2[4 * c + 3], hreg[4 * c + 3], a3);
        }

        // ---- half-batch 1 ----
#pragma unroll
        for (int c = 0; c < 8; c++) {
            ulonglong2 u = h2[16 + 2 * c];
            ulonglong2 v = h2[16 + 2 * c + 1];
            hreg[4 * c + 0] = u.x;
            hreg[4 * c + 1] = u.y;
            hreg[4 * c + 2] = v.x;
            hreg[4 * c + 3] = v.y;
        }
#pragma unroll
        for (int c = 0; c < 8; c++) {
            FMA2(a0, w2[32 + 4 * c + 0], hreg[4 * c + 0], a0);
            FMA2(a1, w2[32 + 4 * c + 1], hreg[4 * c + 1], a1);
            FMA2(a2, w2[32 + 4 * c + 2], hreg[4 * c + 2], a2);
            FMA2(a3, w2[32 + 4 * c + 3], hreg[4 * c + 3], a3);
        }

        ADD2(a0, a0, a1);
        ADD2(a2, a2, a3);
        ADD2(a0, a0, a2);
        float z = __uint_as_float((unsigned)a0)
                + __uint_as_float((unsigned)(a0 >> 32));
        float hn;
        TANHF(hn, z);                 // MUFU.TANH

        hb[p ^ 1][tid] = hn;
        __syncthreads();

        p ^= 1;
        t++;
        s  = sn;
        sn = sn2;
        pre = pren + bsum;
    }

    // Epilogue: h_last is in hb[p].
    float hv = hb[p][tid];
    out[2 * Bb + b * Hh + tid] = hv;               // hidden (1,B,H) at offset 512
    red[0][tid] = W_out[tid] * hv;                 // W_out row 0
    red[1][tid] = W_out[Hh + tid] * hv;            // W_out row 1
    __syncthreads();
    if (tid == 0) {
        float l0 = b_out[0], l1 = b_out[1];
#pragma unroll 8
        for (int i = 0; i < Hh; i++) { l0 += red[0][i]; l1 += red[1][i]; }
        float m  = fmaxf(l0, l1);
        float e0 = __expf(l0 - m), e1 = __expf(l1 - m);
        float inv = __fdividef(1.0f, e0 + e1);
        out[b * 2 + 0] = e0 * inv;                 // fed (B,2) at offset 0
        out[b * 2 + 1] = e1 * inv;
    }
}

// ---------------------------------------------------------------------------
extern "C" void kernel_launch(void* const* d_in, const int* in_sizes, int n_in,
                              void* d_out, int out_size) {
    (void)in_sizes; (void)n_in; (void)out_size;
    const float* x     = (const float*)d_in[0];
    const float* W_ih  = (const float*)d_in[1];
    const float* W_hh  = (const float*)d_in[2];
    const float* b_ih  = (const float*)d_in[3];
    const float* b_hh  = (const float*)d_in[4];
    const float* W_out = (const float*)d_in[5];
    const float* b_out = (const float*)d_in[6];
    float* out = (float*)d_out;

    prep_kernel<<<Bb + 128, 128>>>(x, W_ih);
    schedule_kernel<<<1, Bb>>>();
    sym_kernel<<<(Bb * Tt) / 8, 256>>>(x);
    rnn_kernel<<<Bb, 128>>>(W_hh, b_ih, b_hh, W_out, b_out, out);
}